// round 16
// baseline (speedup 1.0000x reference)
#include <cuda_runtime.h>

// Y: [16384, 2048] fp32, row-major.
// loss = sum_d | 1 - (sum_n Y[n,d]^2) / n |
//
// All LDG-based variants converge at ~5.2 TB/s with DRAM only ~65% active:
// the per-SM L1tex wavefront queue caps in-flight bytes (~12 KB/SM) below
// what 8 TB/s needs (~19 KB/SM). This round streams Y through the TMA bulk
// engine (cp.async.bulk), which bypasses the LSU/L1tex queue entirely.

#define N_ROWS      16384
#define N_COLS      2048
#define COLS4       (N_COLS / 4)          // 512 float4 per row
#define GRID1       296                   // 148 SMs x 2 blocks, one wave
#define CHUNK_ROWS  2
#define CHUNK_FLTS  (CHUNK_ROWS * N_COLS) // 4096 floats
#define CHUNK_BYTES (CHUNK_FLTS * 4)      // 16 KB
#define N_CHUNKS    (N_ROWS / CHUNK_ROWS) // 8192
#define CHUNK_BASE  (N_CHUNKS / GRID1)    // 27
#define CHUNK_REM   (N_CHUNKS % GRID1)    // first 200 blocks take 28

// Scratch (no cudaMalloc allowed).
__device__ float        g_partial[GRID1 * N_COLS];   // 2.4 MB
__device__ unsigned int g_done;    // phase-1 arrival counter
__device__ unsigned int g_done2;   // completion counter (for reset)

__device__ __forceinline__ unsigned int smem_u32(const void* p) {
    return (unsigned int)__cvta_generic_to_shared(p);
}

__device__ __forceinline__ void mbar_init(unsigned int mbar, unsigned int count) {
    asm volatile("mbarrier.init.shared.b64 [%0], %1;" :: "r"(mbar), "r"(count) : "memory");
}
__device__ __forceinline__ void mbar_expect_tx(unsigned int mbar, unsigned int bytes) {
    asm volatile("mbarrier.arrive.expect_tx.shared.b64 _, [%0], %1;"
                 :: "r"(mbar), "r"(bytes) : "memory");
}
__device__ __forceinline__ void mbar_wait(unsigned int mbar, unsigned int parity) {
    asm volatile(
        "{\n\t"
        ".reg .pred P1;\n\t"
        "WAIT_%=:\n\t"
        "mbarrier.try_wait.parity.acquire.cta.shared::cta.b64 P1, [%0], %1, 0x989680;\n\t"
        "@P1 bra.uni DONE_%=;\n\t"
        "bra.uni WAIT_%=;\n\t"
        "DONE_%=:\n\t"
        "}"
        :: "r"(mbar), "r"(parity) : "memory");
}
__device__ __forceinline__ void tma_bulk_ld(unsigned int dst_smem, const void* src,
                                            unsigned int bytes, unsigned int mbar) {
    asm volatile(
        "cp.async.bulk.shared::cluster.global.mbarrier::complete_tx::bytes "
        "[%0], [%1], %2, [%3];"
        :: "r"(dst_smem), "l"(src), "r"(bytes), "r"(mbar) : "memory");
}

// min-blocks=2: all 296 blocks co-resident -> software grid barrier safe.
__global__ __launch_bounds__(512, 2) void semidef_kernel(
    const float* __restrict__ Y, float* __restrict__ out)
{
    const int tid = threadIdx.x;                 // 0..511
    const unsigned int b = blockIdx.x;

    // 2-stage ping-pong buffers; phase-2 tree reduction reuses the space.
    __shared__ __align__(128) union {
        float  buf[2][CHUNK_FLTS];               // 2 x 16 KB
        float4 red[512];                         // phase-2 (after streaming)
    } u;
    __shared__ __align__(8) unsigned long long mbar_full_store[2];

    const unsigned int full0 = smem_u32(&mbar_full_store[0]);
    const unsigned int full1 = smem_u32(&mbar_full_store[1]);

    if (tid == 0) {
        mbar_init(full0, 1);
        mbar_init(full1, 1);
    }
    __syncthreads();

    // Balanced chunk range: blocks [0,200) take 28 chunks, rest take 27.
    const int nchunks = (b < CHUNK_REM) ? (CHUNK_BASE + 1) : CHUNK_BASE;
    const long cstart = (long)b * CHUNK_BASE + (long)min(b, (unsigned int)CHUNK_REM);

    // Prologue: fill both stages.
    if (tid == 0) {
        mbar_expect_tx(full0, CHUNK_BYTES);
        tma_bulk_ld(smem_u32(&u.buf[0][0]), Y + (cstart + 0) * CHUNK_FLTS,
                    CHUNK_BYTES, full0);
        if (nchunks > 1) {
            mbar_expect_tx(full1, CHUNK_BYTES);
            tma_bulk_ld(smem_u32(&u.buf[1][0]), Y + (cstart + 1) * CHUNK_FLTS,
                        CHUNK_BYTES, full1);
        }
    }

    // ---- Phase 1: TMA-fed streaming. Thread t owns columns [4t, 4t+4). ----
    float ax = 0.f, ay = 0.f, az = 0.f, aw = 0.f;
    const int co = tid * 4;

    for (int j = 0; j < nchunks; j++) {
        const int st = j & 1;
        const unsigned int ph = (unsigned int)(j >> 1) & 1u;
        mbar_wait(st ? full1 : full0, ph);

        float4 r0 = *reinterpret_cast<const float4*>(&u.buf[st][co]);
        float4 r1 = *reinterpret_cast<const float4*>(&u.buf[st][N_COLS + co]);
        ax = fmaf(r0.x, r0.x, ax); ay = fmaf(r0.y, r0.y, ay);
        az = fmaf(r0.z, r0.z, az); aw = fmaf(r0.w, r0.w, aw);
        ax = fmaf(r1.x, r1.x, ax); ay = fmaf(r1.y, r1.y, ay);
        az = fmaf(r1.z, r1.z, az); aw = fmaf(r1.w, r1.w, aw);

        __syncthreads();                         // whole block done with stage st

        if (tid == 0 && j + 2 < nchunks) {       // re-arm stage st
            const unsigned int fb = st ? full1 : full0;
            mbar_expect_tx(fb, CHUNK_BYTES);
            tma_bulk_ld(smem_u32(&u.buf[st][0]),
                        Y + (cstart + j + 2) * CHUNK_FLTS, CHUNK_BYTES, fb);
        }
    }

    // Store this block's partial row (2048 floats).
    {
        float4 acc; acc.x = ax; acc.y = ay; acc.z = az; acc.w = aw;
        *reinterpret_cast<float4*>(&g_partial[(long)b * N_COLS + co]) = acc;
    }

    // Zero the scalar output before any phase-2 atomicAdd.
    if (b == 0 && tid == 0) out[0] = 0.0f;

    // ---- Software grid barrier ----
    __threadfence();
    __syncthreads();
    if (tid == 0) {
        atomicAdd(&g_done, 1u);
        volatile unsigned int* vd = &g_done;
        while (*vd < GRID1) { }
    }
    __syncthreads();

    // ---- Phase 2: blocks [0,256) reduce 2 f4-columns each over 296 rows ----
    if (b < 256) {
        const int fc = tid & 1;                  // 0..1
        const int rg = tid >> 1;                 // 0..255
        const int f4col = (int)b * 2 + fc;       // 0..511

        const float4* __restrict__ p = reinterpret_cast<const float4*>(g_partial);
        float4 a = p[(long)rg * COLS4 + f4col];
        if (rg < GRID1 - 256) {                  // fold rows 256..295
            float4 e = p[(long)(rg + 256) * COLS4 + f4col];
            a.x += e.x; a.y += e.y; a.z += e.z; a.w += e.w;
        }

        u.red[tid] = a;                          // index = rg*2 + fc == tid
        __syncthreads();

        #pragma unroll
        for (int stride = 128; stride >= 1; stride >>= 1) {
            if (rg < stride) {
                float4 b2 = u.red[(rg + stride) * 2 + fc];
                float4 a2 = u.red[tid];
                a2.x += b2.x; a2.y += b2.y; a2.z += b2.z; a2.w += b2.w;
                u.red[tid] = a2;
            }
            __syncthreads();
        }

        if (tid == 0) {
            const float inv_n = 1.0f / (float)N_ROWS;
            float total = 0.f;
            #pragma unroll
            for (int f = 0; f < 2; f++) {
                float4 d = u.red[f];
                total += fabsf(1.0f - d.x * inv_n);
                total += fabsf(1.0f - d.y * inv_n);
                total += fabsf(1.0f - d.z * inv_n);
                total += fabsf(1.0f - d.w * inv_n);
            }
            atomicAdd(out, total);
        }
    }

    // Reset counters for the next graph replay: last finishing block only.
    if (tid == 0) {
        unsigned int r2 = atomicAdd(&g_done2, 1u);
        if (r2 == GRID1 - 1) {
            g_done  = 0;
            g_done2 = 0;
        }
    }
}

extern "C" void kernel_launch(void* const* d_in, const int* in_sizes, int n_in,
                              void* d_out, int out_size)
{
    const float* Y = (const float*)d_in[0];
    float* out = (float*)d_out;

    semidef_kernel<<<GRID1, 512>>>(Y, out);
}